// round 3
// baseline (speedup 1.0000x reference)
#include <cuda_runtime.h>
#include <float.h>

#define Bn 4
#define Nn 16384
#define Sn 4096
#define Cin 256
#define Cout 256

typedef unsigned long long u64;

__device__ __forceinline__ u64 pack2(float x, float y) {
    u64 r; asm("mov.b64 %0, {%1,%2};" : "=l"(r) : "f"(x), "f"(y)); return r;
}
__device__ __forceinline__ u64 ffma2(u64 a, u64 b, u64 c) {
    u64 d; asm("fma.rn.f32x2 %0, %1, %2, %3;" : "=l"(d) : "l"(a), "l"(b), "l"(c)); return d;
}

// Scratch (device globals -- allocation-free per harness rules)
__device__ float g_G[Bn * Sn * Cout];   // [b][s][o]  (W @ points2 + bias), 16.8 MB
__device__ float g_w[Bn * Nn * 3];      // interp weights
__device__ int   g_i[Bn * Nn * 3];      // neighbor indices

// ---------------------------------------------------------------------------
// K1: G[b][s][o] = sum_c P[b][c][s] * W[o][c] + bias[o]
// 128x128 tile, K-step 8, 256 threads, 8x8 per thread, f32x2 packed FMA,
// double-buffered smem.
// ---------------------------------------------------------------------------
__global__ __launch_bounds__(256, 2) void k1_gemm(const float* __restrict__ P,
                                                  const float* __restrict__ W,
                                                  const float* __restrict__ bias) {
    __shared__ float sP[2][8][128];   // [buf][k][s]
    __shared__ float sW[2][8][128];   // [buf][k][o]

    const int b  = blockIdx.z;
    const int s0 = blockIdx.x * 128;
    const int o0 = blockIdx.y * 128;
    const int tid = threadIdx.x;
    const int txo = tid & 15;          // o-octet
    const int tys = tid >> 4;          // s-octet
    const int obase = txo * 8;
    const int sbase = tys * 8;

    const float* Pb = P + b * Cin * Sn;

    // loader indices
    const int lk  = tid >> 5;          // 0..7   (P tile k-row)
    const int ls4 = (tid & 31) * 4;    // s offset (float4)
    const int wo  = tid >> 1;          // 0..127 (W tile o-row)
    const int wk  = (tid & 1) * 4;     // k offset (float4)

    u64 acc[8][4];
#pragma unroll
    for (int i = 0; i < 8; i++)
#pragma unroll
        for (int j = 0; j < 4; j++) acc[i][j] = 0ull;

    // prologue: load step 0
    float4 pA = *(const float4*)&Pb[lk * Sn + s0 + ls4];
    float4 pW = *(const float4*)&W[(o0 + wo) * Cin + wk];
    *(float4*)&sP[0][lk][ls4] = pA;
    sW[0][wk + 0][wo] = pW.x;
    sW[0][wk + 1][wo] = pW.y;
    sW[0][wk + 2][wo] = pW.z;
    sW[0][wk + 3][wo] = pW.w;
    __syncthreads();

    for (int step = 0; step < 32; step++) {
        const int cur = step & 1;
        const int nxt = cur ^ 1;
        if (step < 31) {
            const int k0 = (step + 1) * 8;
            pA = *(const float4*)&Pb[(k0 + lk) * Sn + s0 + ls4];
            pW = *(const float4*)&W[(o0 + wo) * Cin + k0 + wk];
        }

#pragma unroll
        for (int k = 0; k < 8; k++) {
            const ulonglong2 w01 = *(const ulonglong2*)&sW[cur][k][obase];
            const ulonglong2 w23 = *(const ulonglong2*)&sW[cur][k][obase + 4];
            const float4 a0 = *(const float4*)&sP[cur][k][sbase];
            const float4 a1 = *(const float4*)&sP[cur][k][sbase + 4];
            const u64 ad[8] = {pack2(a0.x, a0.x), pack2(a0.y, a0.y),
                               pack2(a0.z, a0.z), pack2(a0.w, a0.w),
                               pack2(a1.x, a1.x), pack2(a1.y, a1.y),
                               pack2(a1.z, a1.z), pack2(a1.w, a1.w)};
            const u64 wv[4] = {w01.x, w01.y, w23.x, w23.y};
#pragma unroll
            for (int i = 0; i < 8; i++)
#pragma unroll
                for (int j = 0; j < 4; j++)
                    acc[i][j] = ffma2(ad[i], wv[j], acc[i][j]);
        }

        if (step < 31) {
            *(float4*)&sP[nxt][lk][ls4] = pA;
            sW[nxt][wk + 0][wo] = pW.x;
            sW[nxt][wk + 1][wo] = pW.y;
            sW[nxt][wk + 2][wo] = pW.z;
            sW[nxt][wk + 3][wo] = pW.w;
        }
        __syncthreads();
    }

    // epilogue: fold bias, write G[b][s][o]
    float* Gb = g_G + b * Sn * Cout;
    const float4 bb0 = *(const float4*)&bias[o0 + obase];
    const float4 bb1 = *(const float4*)&bias[o0 + obase + 4];
#pragma unroll
    for (int i = 0; i < 8; i++) {
        const float2 p0 = *(float2*)&acc[i][0];
        const float2 p1 = *(float2*)&acc[i][1];
        const float2 p2 = *(float2*)&acc[i][2];
        const float2 p3 = *(float2*)&acc[i][3];
        float4 v0, v1;
        v0.x = p0.x + bb0.x; v0.y = p0.y + bb0.y;
        v0.z = p1.x + bb0.z; v0.w = p1.y + bb0.w;
        v1.x = p2.x + bb1.x; v1.y = p2.y + bb1.y;
        v1.z = p3.x + bb1.z; v1.w = p3.y + bb1.w;
        float* row = &Gb[(s0 + sbase + i) * Cout + o0 + obase];
        *(float4*)&row[0] = v0;
        *(float4*)&row[4] = v1;
    }
}

// ---------------------------------------------------------------------------
// K2: 3-NN search. 128 threads x 4 points/thread = 512 points/CTA -> 128 CTAs.
// xyz2 staged in smem as (-2x,-2y,-2z,|p|^2); rank value is 3 FMAs/point.
// ---------------------------------------------------------------------------
__global__ __launch_bounds__(128) void k2_knn(const float* __restrict__ xyz1,
                                              const float* __restrict__ xyz2) {
    extern __shared__ unsigned char smem_raw[];
    float4* qtab = (float4*)smem_raw;   // [Sn] = 64 KB

    const int b   = blockIdx.y;
    const int n0  = blockIdx.x * 512;
    const int tid = threadIdx.x;

    const float* x2 = xyz2 + b * 3 * Sn;
    for (int s = tid; s < Sn; s += 128) {
        const float x = x2[s];
        const float y = x2[Sn + s];
        const float z = x2[2 * Sn + s];
        qtab[s] = make_float4(-2.f * x, -2.f * y, -2.f * z, x * x + y * y + z * z);
    }
    __syncthreads();

    const float* x1 = xyz1 + b * 3 * Nn;
    float px[4], py[4], pz[4], d0[4], d1[4], d2[4];
    int i0[4], i1[4], i2[4];
#pragma unroll
    for (int j = 0; j < 4; j++) {
        const int n = n0 + tid + j * 128;
        px[j] = x1[n];
        py[j] = x1[Nn + n];
        pz[j] = x1[2 * Nn + n];
        d0[j] = FLT_MAX; d1[j] = FLT_MAX; d2[j] = FLT_MAX;
        i0[j] = 0; i1[j] = 0; i2[j] = 0;
    }

#pragma unroll 4
    for (int s = 0; s < Sn; s++) {
        const float4 q = qtab[s];
        float e[4];
#pragma unroll
        for (int j = 0; j < 4; j++)
            e[j] = fmaf(px[j], q.x, fmaf(py[j], q.y, fmaf(pz[j], q.z, q.w)));
        if ((e[0] < d2[0]) | (e[1] < d2[1]) | (e[2] < d2[2]) | (e[3] < d2[3])) {
#pragma unroll
            for (int j = 0; j < 4; j++) {
                const float ej = e[j];
                if (ej < d2[j]) {
                    if (ej < d0[j]) {
                        d2[j] = d1[j]; i2[j] = i1[j];
                        d1[j] = d0[j]; i1[j] = i0[j];
                        d0[j] = ej;    i0[j] = s;
                    } else if (ej < d1[j]) {
                        d2[j] = d1[j]; i2[j] = i1[j];
                        d1[j] = ej;    i1[j] = s;
                    } else {
                        d2[j] = ej;    i2[j] = s;
                    }
                }
            }
        }
    }

#pragma unroll
    for (int j = 0; j < 4; j++) {
        const int n = n0 + tid + j * 128;
        const float pn = px[j] * px[j] + py[j] * py[j] + pz[j] * pz[j];
        const float r0 = 1.f / (d0[j] + pn + 1e-8f);
        const float r1 = 1.f / (d1[j] + pn + 1e-8f);
        const float r2 = 1.f / (d2[j] + pn + 1e-8f);
        const float inv = 1.f / (r0 + r1 + r2);
        const int base = (b * Nn + n) * 3;
        g_w[base + 0] = r0 * inv;
        g_w[base + 1] = r1 * inv;
        g_w[base + 2] = r2 * inv;
        g_i[base + 0] = i0[j];
        g_i[base + 1] = i1[j];
        g_i[base + 2] = i2[j];
    }
}

// ---------------------------------------------------------------------------
// K3: gather + weighted sum + transpose-write.
// CTA = (b, tile of 64 points), 256 threads (one per output channel).
// ---------------------------------------------------------------------------
#define ACC_PITCH 261

__global__ void k3_gather(float* __restrict__ out) {
    extern __shared__ unsigned char smem_raw[];
    float* acc = (float*)smem_raw;            // [64][ACC_PITCH]
    __shared__ float sw[64 * 3];
    __shared__ int   si[64 * 3];

    const int b   = blockIdx.y;
    const int n0  = blockIdx.x * 64;
    const int tid = threadIdx.x;

    for (int t = tid; t < 64 * 3; t += 256) {
        sw[t] = g_w[(b * Nn + n0) * 3 + t];
        si[t] = g_i[(b * Nn + n0) * 3 + t];
    }
    __syncthreads();

    const float* Gb = g_G + b * Sn * Cout;
    const int o = tid;

#pragma unroll 4
    for (int p = 0; p < 64; p++) {
        const float w0 = sw[3 * p + 0];
        const float w1 = sw[3 * p + 1];
        const float w2 = sw[3 * p + 2];
        const int   j0 = si[3 * p + 0];
        const int   j1 = si[3 * p + 1];
        const int   j2 = si[3 * p + 2];
        float v = w0 * Gb[j0 * Cout + o];
        v = fmaf(w1, Gb[j1 * Cout + o], v);
        v = fmaf(w2, Gb[j2 * Cout + o], v);
        acc[p * ACC_PITCH + o] = v;
    }
    __syncthreads();

    float* ob = out + b * Cout * Nn;
    for (int idx = tid; idx < 256 * 16; idx += 256) {
        const int c = idx >> 4;
        const int g = idx & 15;
        float4 v;
        v.x = acc[(4 * g + 0) * ACC_PITCH + c];
        v.y = acc[(4 * g + 1) * ACC_PITCH + c];
        v.z = acc[(4 * g + 2) * ACC_PITCH + c];
        v.w = acc[(4 * g + 3) * ACC_PITCH + c];
        *(float4*)&ob[c * Nn + n0 + 4 * g] = v;
    }
}

// ---------------------------------------------------------------------------
extern "C" void kernel_launch(void* const* d_in, const int* in_sizes, int n_in,
                              void* d_out, int out_size) {
    const float* xyz1 = (const float*)d_in[0];   // [B,3,N]
    const float* xyz2 = (const float*)d_in[1];   // [B,3,S]
    const float* P    = (const float*)d_in[2];   // [B,Cin,S]
    const float* W    = (const float*)d_in[3];   // [Cout,Cin]
    const float* bias = (const float*)d_in[4];   // [Cout]
    float* out = (float*)d_out;                  // [B,Cout,N]

    // lazy one-time handles; first call (correctness run) happens before capture
    static cudaStream_t s2 = nullptr;
    static cudaEvent_t evFork = nullptr, evJoin = nullptr;
    if (!s2) {
        cudaStreamCreateWithFlags(&s2, cudaStreamNonBlocking);
        cudaEventCreateWithFlags(&evFork, cudaEventDisableTiming);
        cudaEventCreateWithFlags(&evJoin, cudaEventDisableTiming);
        cudaFuncSetAttribute(k2_knn, cudaFuncAttributeMaxDynamicSharedMemorySize,
                             Sn * (int)sizeof(float4));
        cudaFuncSetAttribute(k3_gather, cudaFuncAttributeMaxDynamicSharedMemorySize,
                             64 * ACC_PITCH * (int)sizeof(float));
    }

    // fork: k2 (xyz only) runs concurrently with k1 (points2/W only)
    cudaEventRecord(evFork, 0);
    cudaStreamWaitEvent(s2, evFork, 0);

    k1_gemm<<<dim3(Sn / 128, Cout / 128, Bn), 256>>>(P, W, bias);
    k2_knn<<<dim3(Nn / 512, Bn), 128, Sn * sizeof(float4), s2>>>(xyz1, xyz2);

    // join
    cudaEventRecord(evJoin, s2);
    cudaStreamWaitEvent(0, evJoin, 0);

    k3_gather<<<dim3(Nn / 64, Bn), 256, 64 * ACC_PITCH * sizeof(float)>>>(out);
}

// round 6
// speedup vs baseline: 1.3378x; 1.3378x over previous
#include <cuda_runtime.h>
#include <float.h>

#define Bn 4
#define Nn 16384
#define Sn 4096
#define Cin 256
#define Cout 256

typedef unsigned long long u64;

__device__ __forceinline__ u64 pack2(float x, float y) {
    u64 r; asm("mov.b64 %0, {%1,%2};" : "=l"(r) : "f"(x), "f"(y)); return r;
}
__device__ __forceinline__ u64 ffma2(u64 a, u64 b, u64 c) {
    u64 d; asm("fma.rn.f32x2 %0, %1, %2, %3;" : "=l"(d) : "l"(a), "l"(b), "l"(c)); return d;
}

// Scratch (device globals -- allocation-free per harness rules)
__device__ float g_G[Bn * Sn * Cout];   // [b][s][o]  (W @ points2 + bias), 16.8 MB
__device__ float g_w[Bn * Nn * 3];      // interp weights
__device__ int   g_i[Bn * Nn * 3];      // neighbor indices

// ---------------------------------------------------------------------------
// K1: G[b][s][o] = sum_c P[b][c][s] * W[o][c] + bias[o]
// 128x128 tile, K-step 8, 256 threads, 8x8 per thread, f32x2 packed FMA,
// double-buffered smem.  (Measured 57.8us -- unchanged from last round.)
// ---------------------------------------------------------------------------
__global__ __launch_bounds__(256, 2) void k1_gemm(const float* __restrict__ P,
                                                  const float* __restrict__ W,
                                                  const float* __restrict__ bias) {
    __shared__ float sP[2][8][128];   // [buf][k][s]
    __shared__ float sW[2][8][128];   // [buf][k][o]

    const int b  = blockIdx.z;
    const int s0 = blockIdx.x * 128;
    const int o0 = blockIdx.y * 128;
    const int tid = threadIdx.x;
    const int txo = tid & 15;          // o-octet
    const int tys = tid >> 4;          // s-octet
    const int obase = txo * 8;
    const int sbase = tys * 8;

    const float* Pb = P + b * Cin * Sn;

    // loader indices
    const int lk  = tid >> 5;          // 0..7   (P tile k-row)
    const int ls4 = (tid & 31) * 4;    // s offset (float4)
    const int wo  = tid >> 1;          // 0..127 (W tile o-row)
    const int wk  = (tid & 1) * 4;     // k offset (float4)

    u64 acc[8][4];
#pragma unroll
    for (int i = 0; i < 8; i++)
#pragma unroll
        for (int j = 0; j < 4; j++) acc[i][j] = 0ull;

    // prologue: load step 0
    float4 pA = *(const float4*)&Pb[lk * Sn + s0 + ls4];
    float4 pW = *(const float4*)&W[(o0 + wo) * Cin + wk];
    *(float4*)&sP[0][lk][ls4] = pA;
    sW[0][wk + 0][wo] = pW.x;
    sW[0][wk + 1][wo] = pW.y;
    sW[0][wk + 2][wo] = pW.z;
    sW[0][wk + 3][wo] = pW.w;
    __syncthreads();

    for (int step = 0; step < 32; step++) {
        const int cur = step & 1;
        const int nxt = cur ^ 1;
        if (step < 31) {
            const int k0 = (step + 1) * 8;
            pA = *(const float4*)&Pb[(k0 + lk) * Sn + s0 + ls4];
            pW = *(const float4*)&W[(o0 + wo) * Cin + k0 + wk];
        }

#pragma unroll
        for (int k = 0; k < 8; k++) {
            const ulonglong2 w01 = *(const ulonglong2*)&sW[cur][k][obase];
            const ulonglong2 w23 = *(const ulonglong2*)&sW[cur][k][obase + 4];
            const float4 a0 = *(const float4*)&sP[cur][k][sbase];
            const float4 a1 = *(const float4*)&sP[cur][k][sbase + 4];
            const u64 ad[8] = {pack2(a0.x, a0.x), pack2(a0.y, a0.y),
                               pack2(a0.z, a0.z), pack2(a0.w, a0.w),
                               pack2(a1.x, a1.x), pack2(a1.y, a1.y),
                               pack2(a1.z, a1.z), pack2(a1.w, a1.w)};
            const u64 wv[4] = {w01.x, w01.y, w23.x, w23.y};
#pragma unroll
            for (int i = 0; i < 8; i++)
#pragma unroll
                for (int j = 0; j < 4; j++)
                    acc[i][j] = ffma2(ad[i], wv[j], acc[i][j]);
        }

        if (step < 31) {
            *(float4*)&sP[nxt][lk][ls4] = pA;
            sW[nxt][wk + 0][wo] = pW.x;
            sW[nxt][wk + 1][wo] = pW.y;
            sW[nxt][wk + 2][wo] = pW.z;
            sW[nxt][wk + 3][wo] = pW.w;
        }
        __syncthreads();
    }

    // epilogue: fold bias, write G[b][s][o]
    float* Gb = g_G + b * Sn * Cout;
    const float4 bb0 = *(const float4*)&bias[o0 + obase];
    const float4 bb1 = *(const float4*)&bias[o0 + obase + 4];
#pragma unroll
    for (int i = 0; i < 8; i++) {
        const float2 p0 = *(float2*)&acc[i][0];
        const float2 p1 = *(float2*)&acc[i][1];
        const float2 p2 = *(float2*)&acc[i][2];
        const float2 p3 = *(float2*)&acc[i][3];
        float4 v0, v1;
        v0.x = p0.x + bb0.x; v0.y = p0.y + bb0.y;
        v0.z = p1.x + bb0.z; v0.w = p1.y + bb0.w;
        v1.x = p2.x + bb1.x; v1.y = p2.y + bb1.y;
        v1.z = p3.x + bb1.z; v1.w = p3.y + bb1.w;
        float* row = &Gb[(s0 + sbase + i) * Cout + o0 + obase];
        *(float4*)&row[0] = v0;
        *(float4*)&row[4] = v1;
    }
}

// ---------------------------------------------------------------------------
// K2: 3-NN search. 256 threads x 2 points/thread = 512 points/CTA
// -> grid 32 x 4 = 128 CTAs (~one full wave, 8 warps/CTA).
// xyz2 staged in smem as (-2x,-2y,-2z,|p|^2); one broadcast LDS.128
// amortized over 2 points; per-point insert branches (R1-proven form).
// ---------------------------------------------------------------------------
__global__ __launch_bounds__(256) void k2_knn(const float* __restrict__ xyz1,
                                              const float* __restrict__ xyz2) {
    extern __shared__ unsigned char smem_raw[];
    float4* qtab = (float4*)smem_raw;   // [Sn] = 64 KB

    const int b   = blockIdx.y;
    const int n0  = blockIdx.x * 512;
    const int tid = threadIdx.x;

    const float* x2 = xyz2 + b * 3 * Sn;
    for (int s = tid; s < Sn; s += 256) {
        const float x = x2[s];
        const float y = x2[Sn + s];
        const float z = x2[2 * Sn + s];
        qtab[s] = make_float4(-2.f * x, -2.f * y, -2.f * z, x * x + y * y + z * z);
    }
    __syncthreads();

    const float* x1 = xyz1 + b * 3 * Nn;
    const int nA = n0 + tid;
    const int nB = n0 + tid + 256;

    const float pxA = x1[nA], pyA = x1[Nn + nA], pzA = x1[2 * Nn + nA];
    const float pxB = x1[nB], pyB = x1[Nn + nB], pzB = x1[2 * Nn + nB];

    float d0A = FLT_MAX, d1A = FLT_MAX, d2A = FLT_MAX;
    float d0B = FLT_MAX, d1B = FLT_MAX, d2B = FLT_MAX;
    int i0A = 0, i1A = 0, i2A = 0, i0B = 0, i1B = 0, i2B = 0;

#pragma unroll 4
    for (int s = 0; s < Sn; s++) {
        const float4 q = qtab[s];
        const float eA = fmaf(pxA, q.x, fmaf(pyA, q.y, fmaf(pzA, q.z, q.w)));
        const float eB = fmaf(pxB, q.x, fmaf(pyB, q.y, fmaf(pzB, q.z, q.w)));
        if (eA < d2A) {
            if (eA < d0A)      { d2A = d1A; i2A = i1A; d1A = d0A; i1A = i0A; d0A = eA; i0A = s; }
            else if (eA < d1A) { d2A = d1A; i2A = i1A; d1A = eA;  i1A = s; }
            else               { d2A = eA;  i2A = s; }
        }
        if (eB < d2B) {
            if (eB < d0B)      { d2B = d1B; i2B = i1B; d1B = d0B; i1B = i0B; d0B = eB; i0B = s; }
            else if (eB < d1B) { d2B = d1B; i2B = i1B; d1B = eB;  i1B = s; }
            else               { d2B = eB;  i2B = s; }
        }
    }

    {
        const float pn = pxA * pxA + pyA * pyA + pzA * pzA;
        const float r0 = 1.f / (d0A + pn + 1e-8f);
        const float r1 = 1.f / (d1A + pn + 1e-8f);
        const float r2 = 1.f / (d2A + pn + 1e-8f);
        const float inv = 1.f / (r0 + r1 + r2);
        const int base = (b * Nn + nA) * 3;
        g_w[base + 0] = r0 * inv;
        g_w[base + 1] = r1 * inv;
        g_w[base + 2] = r2 * inv;
        g_i[base + 0] = i0A;
        g_i[base + 1] = i1A;
        g_i[base + 2] = i2A;
    }
    {
        const float pn = pxB * pxB + pyB * pyB + pzB * pzB;
        const float r0 = 1.f / (d0B + pn + 1e-8f);
        const float r1 = 1.f / (d1B + pn + 1e-8f);
        const float r2 = 1.f / (d2B + pn + 1e-8f);
        const float inv = 1.f / (r0 + r1 + r2);
        const int base = (b * Nn + nB) * 3;
        g_w[base + 0] = r0 * inv;
        g_w[base + 1] = r1 * inv;
        g_w[base + 2] = r2 * inv;
        g_i[base + 0] = i0B;
        g_i[base + 1] = i1B;
        g_i[base + 2] = i2B;
    }
}

// ---------------------------------------------------------------------------
// K3: gather + weighted sum + transpose-write.
// CTA = (b, tile of 64 points), 256 threads (one per output channel).
// ---------------------------------------------------------------------------
#define ACC_PITCH 261

__global__ void k3_gather(float* __restrict__ out) {
    extern __shared__ unsigned char smem_raw[];
    float* acc = (float*)smem_raw;            // [64][ACC_PITCH]
    __shared__ float sw[64 * 3];
    __shared__ int   si[64 * 3];

    const int b   = blockIdx.y;
    const int n0  = blockIdx.x * 64;
    const int tid = threadIdx.x;

    for (int t = tid; t < 64 * 3; t += 256) {
        sw[t] = g_w[(b * Nn + n0) * 3 + t];
        si[t] = g_i[(b * Nn + n0) * 3 + t];
    }
    __syncthreads();

    const float* Gb = g_G + b * Sn * Cout;
    const int o = tid;

#pragma unroll 4
    for (int p = 0; p < 64; p++) {
        const float w0 = sw[3 * p + 0];
        const float w1 = sw[3 * p + 1];
        const float w2 = sw[3 * p + 2];
        const int   j0 = si[3 * p + 0];
        const int   j1 = si[3 * p + 1];
        const int   j2 = si[3 * p + 2];
        float v = w0 * Gb[j0 * Cout + o];
        v = fmaf(w1, Gb[j1 * Cout + o], v);
        v = fmaf(w2, Gb[j2 * Cout + o], v);
        acc[p * ACC_PITCH + o] = v;
    }
    __syncthreads();

    float* ob = out + b * Cout * Nn;
    for (int idx = tid; idx < 256 * 16; idx += 256) {
        const int c = idx >> 4;
        const int g = idx & 15;
        float4 v;
        v.x = acc[(4 * g + 0) * ACC_PITCH + c];
        v.y = acc[(4 * g + 1) * ACC_PITCH + c];
        v.z = acc[(4 * g + 2) * ACC_PITCH + c];
        v.w = acc[(4 * g + 3) * ACC_PITCH + c];
        *(float4*)&ob[c * Nn + n0 + 4 * g] = v;
    }
}

// ---------------------------------------------------------------------------
extern "C" void kernel_launch(void* const* d_in, const int* in_sizes, int n_in,
                              void* d_out, int out_size) {
    const float* xyz1 = (const float*)d_in[0];   // [B,3,N]
    const float* xyz2 = (const float*)d_in[1];   // [B,3,S]
    const float* P    = (const float*)d_in[2];   // [B,Cin,S]
    const float* W    = (const float*)d_in[3];   // [Cout,Cin]
    const float* bias = (const float*)d_in[4];   // [Cout]
    float* out = (float*)d_out;                  // [B,Cout,N]

    cudaFuncSetAttribute(k2_knn, cudaFuncAttributeMaxDynamicSharedMemorySize,
                         Sn * (int)sizeof(float4));
    cudaFuncSetAttribute(k3_gather, cudaFuncAttributeMaxDynamicSharedMemorySize,
                         64 * ACC_PITCH * (int)sizeof(float));

    k1_gemm<<<dim3(Sn / 128, Cout / 128, Bn), 256>>>(P, W, bias);
    k2_knn<<<dim3(Nn / 512, Bn), 256, Sn * sizeof(float4)>>>(xyz1, xyz2);
    k3_gather<<<dim3(Nn / 64, Bn), 256, 64 * ACC_PITCH * sizeof(float)>>>(out);
}

// round 7
// speedup vs baseline: 2.0181x; 1.5085x over previous
#include <cuda_runtime.h>
#include <float.h>

#define Bn 4
#define Nn 16384
#define Sn 4096
#define Cin 256
#define Cout 256

#define SPLITS 4
#define SCHUNK (Sn / SPLITS)   // 1024 candidates per CTA

typedef unsigned long long u64;

__device__ __forceinline__ u64 pack2(float x, float y) {
    u64 r; asm("mov.b64 %0, {%1,%2};" : "=l"(r) : "f"(x), "f"(y)); return r;
}
__device__ __forceinline__ u64 ffma2(u64 a, u64 b, u64 c) {
    u64 d; asm("fma.rn.f32x2 %0, %1, %2, %3;" : "=l"(d) : "l"(a), "l"(b), "l"(c)); return d;
}

// Scratch (device globals -- allocation-free per harness rules)
__device__ float g_G[Bn * Sn * Cout];            // [b][s][o], 16.8 MB
__device__ float g_w[Bn * Nn * 3];               // final interp weights
__device__ int   g_i[Bn * Nn * 3];               // final neighbor indices
__device__ float g_pd[SPLITS * Bn * Nn * 3];     // partial top-3 rank values
__device__ int   g_pi[SPLITS * Bn * Nn * 3];     // partial top-3 indices

// ---------------------------------------------------------------------------
// K1: G[b][s][o] = sum_c P[b][c][s] * W[o][c] + bias[o]
// 128x128 tile, K-step 8, 256 threads, 8x8 per thread, f32x2 packed FMA,
// double-buffered smem.  (Measured 58us -- unchanged.)
// ---------------------------------------------------------------------------
__global__ __launch_bounds__(256, 2) void k1_gemm(const float* __restrict__ P,
                                                  const float* __restrict__ W,
                                                  const float* __restrict__ bias) {
    __shared__ float sP[2][8][128];   // [buf][k][s]
    __shared__ float sW[2][8][128];   // [buf][k][o]

    const int b  = blockIdx.z;
    const int s0 = blockIdx.x * 128;
    const int o0 = blockIdx.y * 128;
    const int tid = threadIdx.x;
    const int txo = tid & 15;
    const int tys = tid >> 4;
    const int obase = txo * 8;
    const int sbase = tys * 8;

    const float* Pb = P + b * Cin * Sn;

    const int lk  = tid >> 5;
    const int ls4 = (tid & 31) * 4;
    const int wo  = tid >> 1;
    const int wk  = (tid & 1) * 4;

    u64 acc[8][4];
#pragma unroll
    for (int i = 0; i < 8; i++)
#pragma unroll
        for (int j = 0; j < 4; j++) acc[i][j] = 0ull;

    float4 pA = *(const float4*)&Pb[lk * Sn + s0 + ls4];
    float4 pW = *(const float4*)&W[(o0 + wo) * Cin + wk];
    *(float4*)&sP[0][lk][ls4] = pA;
    sW[0][wk + 0][wo] = pW.x;
    sW[0][wk + 1][wo] = pW.y;
    sW[0][wk + 2][wo] = pW.z;
    sW[0][wk + 3][wo] = pW.w;
    __syncthreads();

    for (int step = 0; step < 32; step++) {
        const int cur = step & 1;
        const int nxt = cur ^ 1;
        if (step < 31) {
            const int k0 = (step + 1) * 8;
            pA = *(const float4*)&Pb[(k0 + lk) * Sn + s0 + ls4];
            pW = *(const float4*)&W[(o0 + wo) * Cin + k0 + wk];
        }

#pragma unroll
        for (int k = 0; k < 8; k++) {
            const ulonglong2 w01 = *(const ulonglong2*)&sW[cur][k][obase];
            const ulonglong2 w23 = *(const ulonglong2*)&sW[cur][k][obase + 4];
            const float4 a0 = *(const float4*)&sP[cur][k][sbase];
            const float4 a1 = *(const float4*)&sP[cur][k][sbase + 4];
            const u64 ad[8] = {pack2(a0.x, a0.x), pack2(a0.y, a0.y),
                               pack2(a0.z, a0.z), pack2(a0.w, a0.w),
                               pack2(a1.x, a1.x), pack2(a1.y, a1.y),
                               pack2(a1.z, a1.z), pack2(a1.w, a1.w)};
            const u64 wv[4] = {w01.x, w01.y, w23.x, w23.y};
#pragma unroll
            for (int i = 0; i < 8; i++)
#pragma unroll
                for (int j = 0; j < 4; j++)
                    acc[i][j] = ffma2(ad[i], wv[j], acc[i][j]);
        }

        if (step < 31) {
            *(float4*)&sP[nxt][lk][ls4] = pA;
            sW[nxt][wk + 0][wo] = pW.x;
            sW[nxt][wk + 1][wo] = pW.y;
            sW[nxt][wk + 2][wo] = pW.z;
            sW[nxt][wk + 3][wo] = pW.w;
        }
        __syncthreads();
    }

    float* Gb = g_G + b * Sn * Cout;
    const float4 bb0 = *(const float4*)&bias[o0 + obase];
    const float4 bb1 = *(const float4*)&bias[o0 + obase + 4];
#pragma unroll
    for (int i = 0; i < 8; i++) {
        const float2 p0 = *(float2*)&acc[i][0];
        const float2 p1 = *(float2*)&acc[i][1];
        const float2 p2 = *(float2*)&acc[i][2];
        const float2 p3 = *(float2*)&acc[i][3];
        float4 v0, v1;
        v0.x = p0.x + bb0.x; v0.y = p0.y + bb0.y;
        v0.z = p1.x + bb0.z; v0.w = p1.y + bb0.w;
        v1.x = p2.x + bb1.x; v1.y = p2.y + bb1.y;
        v1.z = p3.x + bb1.z; v1.w = p3.y + bb1.w;
        float* row = &Gb[(s0 + sbase + i) * Cout + o0 + obase];
        *(float4*)&row[0] = v0;
        *(float4*)&row[4] = v1;
    }
}

// ---------------------------------------------------------------------------
// K2a: partial 3-NN over one S-chunk. 1 point/thread (R1-proven inner loop),
// grid (Nn/256, SPLITS, Bn) = 1024 CTAs -> high occupancy, 16 KB table.
// ---------------------------------------------------------------------------
__global__ __launch_bounds__(256) void k2_partial(const float* __restrict__ xyz1,
                                                  const float* __restrict__ xyz2) {
    __shared__ float4 qtab[SCHUNK];   // 16 KB

    const int b   = blockIdx.z;
    const int sp  = blockIdx.y;
    const int n0  = blockIdx.x * 256;
    const int tid = threadIdx.x;
    const int sb  = sp * SCHUNK;

    const float* x2 = xyz2 + b * 3 * Sn;
    for (int s = tid; s < SCHUNK; s += 256) {
        const float x = x2[sb + s];
        const float y = x2[Sn + sb + s];
        const float z = x2[2 * Sn + sb + s];
        qtab[s] = make_float4(-2.f * x, -2.f * y, -2.f * z, x * x + y * y + z * z);
    }
    __syncthreads();

    const int n = n0 + tid;
    const float* x1 = xyz1 + b * 3 * Nn;
    const float px = x1[n];
    const float py = x1[Nn + n];
    const float pz = x1[2 * Nn + n];

    float d0 = FLT_MAX, d1 = FLT_MAX, d2 = FLT_MAX;
    int   i0 = 0, i1 = 0, i2 = 0;

#pragma unroll 4
    for (int s = 0; s < SCHUNK; s++) {
        const float4 q = qtab[s];
        const float e = fmaf(px, q.x, fmaf(py, q.y, fmaf(pz, q.z, q.w)));
        if (e < d2) {
            if (e < d0)      { d2 = d1; i2 = i1; d1 = d0; i1 = i0; d0 = e; i0 = sb + s; }
            else if (e < d1) { d2 = d1; i2 = i1; d1 = e;  i1 = sb + s; }
            else             { d2 = e;  i2 = sb + s; }
        }
    }

    const int base = ((sp * Bn + b) * Nn + n) * 3;
    g_pd[base + 0] = d0;
    g_pd[base + 1] = d1;
    g_pd[base + 2] = d2;
    g_pi[base + 0] = i0;
    g_pi[base + 1] = i1;
    g_pi[base + 2] = i2;
}

// ---------------------------------------------------------------------------
// K2b: merge SPLITS sorted triples per point, compute interp weights.
// Sequential insertion with strict < preserves top_k lowest-index tie-break
// (split order == index order).
// ---------------------------------------------------------------------------
__global__ __launch_bounds__(256) void k2_merge(const float* __restrict__ xyz1) {
    const int t = blockIdx.x * 256 + threadIdx.x;   // 0 .. Bn*Nn-1
    const int b = t >> 14;                          // Nn = 16384
    const int n = t & (Nn - 1);

    float d0 = FLT_MAX, d1 = FLT_MAX, d2 = FLT_MAX;
    int   i0 = 0, i1 = 0, i2 = 0;

#pragma unroll
    for (int sp = 0; sp < SPLITS; sp++) {
        const int base = ((sp * Bn + b) * Nn + n) * 3;
#pragma unroll
        for (int r = 0; r < 3; r++) {
            const float e  = g_pd[base + r];
            const int   id = g_pi[base + r];
            if (e < d2) {
                if (e < d0)      { d2 = d1; i2 = i1; d1 = d0; i1 = i0; d0 = e; i0 = id; }
                else if (e < d1) { d2 = d1; i2 = i1; d1 = e;  i1 = id; }
                else             { d2 = e;  i2 = id; }
            }
        }
    }

    const float* x1 = xyz1 + b * 3 * Nn;
    const float px = x1[n], py = x1[Nn + n], pz = x1[2 * Nn + n];
    const float pn = px * px + py * py + pz * pz;
    const float r0 = 1.f / (d0 + pn + 1e-8f);
    const float r1 = 1.f / (d1 + pn + 1e-8f);
    const float r2 = 1.f / (d2 + pn + 1e-8f);
    const float inv = 1.f / (r0 + r1 + r2);

    const int base = (b * Nn + n) * 3;
    g_w[base + 0] = r0 * inv;
    g_w[base + 1] = r1 * inv;
    g_w[base + 2] = r2 * inv;
    g_i[base + 0] = i0;
    g_i[base + 1] = i1;
    g_i[base + 2] = i2;
}

// ---------------------------------------------------------------------------
// K3: gather + weighted sum + transpose-write. (R1-proven, unchanged.)
// ---------------------------------------------------------------------------
#define ACC_PITCH 261

__global__ void k3_gather(float* __restrict__ out) {
    extern __shared__ unsigned char smem_raw[];
    float* acc = (float*)smem_raw;            // [64][ACC_PITCH]
    __shared__ float sw[64 * 3];
    __shared__ int   si[64 * 3];

    const int b   = blockIdx.y;
    const int n0  = blockIdx.x * 64;
    const int tid = threadIdx.x;

    for (int t = tid; t < 64 * 3; t += 256) {
        sw[t] = g_w[(b * Nn + n0) * 3 + t];
        si[t] = g_i[(b * Nn + n0) * 3 + t];
    }
    __syncthreads();

    const float* Gb = g_G + b * Sn * Cout;
    const int o = tid;

#pragma unroll 4
    for (int p = 0; p < 64; p++) {
        const float w0 = sw[3 * p + 0];
        const float w1 = sw[3 * p + 1];
        const float w2 = sw[3 * p + 2];
        const int   j0 = si[3 * p + 0];
        const int   j1 = si[3 * p + 1];
        const int   j2 = si[3 * p + 2];
        float v = w0 * Gb[j0 * Cout + o];
        v = fmaf(w1, Gb[j1 * Cout + o], v);
        v = fmaf(w2, Gb[j2 * Cout + o], v);
        acc[p * ACC_PITCH + o] = v;
    }
    __syncthreads();

    float* ob = out + b * Cout * Nn;
    for (int idx = tid; idx < 256 * 16; idx += 256) {
        const int c = idx >> 4;
        const int g = idx & 15;
        float4 v;
        v.x = acc[(4 * g + 0) * ACC_PITCH + c];
        v.y = acc[(4 * g + 1) * ACC_PITCH + c];
        v.z = acc[(4 * g + 2) * ACC_PITCH + c];
        v.w = acc[(4 * g + 3) * ACC_PITCH + c];
        *(float4*)&ob[c * Nn + n0 + 4 * g] = v;
    }
}

// ---------------------------------------------------------------------------
extern "C" void kernel_launch(void* const* d_in, const int* in_sizes, int n_in,
                              void* d_out, int out_size) {
    const float* xyz1 = (const float*)d_in[0];   // [B,3,N]
    const float* xyz2 = (const float*)d_in[1];   // [B,3,S]
    const float* P    = (const float*)d_in[2];   // [B,Cin,S]
    const float* W    = (const float*)d_in[3];   // [Cout,Cin]
    const float* bias = (const float*)d_in[4];   // [Cout]
    float* out = (float*)d_out;                  // [B,Cout,N]

    cudaFuncSetAttribute(k3_gather, cudaFuncAttributeMaxDynamicSharedMemorySize,
                         64 * ACC_PITCH * (int)sizeof(float));

    k1_gemm<<<dim3(Sn / 128, Cout / 128, Bn), 256>>>(P, W, bias);
    k2_partial<<<dim3(Nn / 256, SPLITS, Bn), 256>>>(xyz1, xyz2);
    k2_merge<<<(Bn * Nn) / 256, 256>>>(xyz1);
    k3_gather<<<dim3(Nn / 64, Bn), 256, 64 * ACC_PITCH * sizeof(float)>>>(out);
}